// round 4
// baseline (speedup 1.0000x reference)
#include <cuda_runtime.h>
#include <math.h>
#include <stdint.h>

#define BATCH 4
#define CFULL 512
#define HC 256
#define HH 128
#define WW 128
#define HW (HH*WW)

// g_x1 is TRANSPOSED: [b][n(pixel)][k(channel)], k contiguous (256 floats/row)
__device__ float g_x1[BATCH * HW * HC];
__device__ float g_pool[BATCH * HC * 4];
__device__ float g_base[BATCH * 4 * CFULL];

// ---------------------------------------------------------------------------
// Kernel 1: adaptive max pool of channels 256..511 to 2x2 (float4 loads)
// ---------------------------------------------------------------------------
__global__ __launch_bounds__(256) void pool_kernel(const float* __restrict__ x) {
    int blk = blockIdx.x;
    int q  = blk & 3;
    int cc = (blk >> 2) & 255;
    int b  = blk >> 10;
    int qh = q >> 1, qw = q & 1;
    const float* xin = x + ((size_t)(b * CFULL + 256 + cc)) * HW + qh * 64 * WW + qw * 64;
    const float4* xin4 = reinterpret_cast<const float4*>(xin);

    float m = -INFINITY;
    for (int i = threadIdx.x; i < 1024; i += 256) {
        int r = i >> 4, c4 = i & 15;
        float4 v = xin4[r * 32 + c4];
        m = fmaxf(m, fmaxf(fmaxf(v.x, v.y), fmaxf(v.z, v.w)));
    }
    __shared__ float red[256];
    red[threadIdx.x] = m;
    __syncthreads();
    for (int s = 128; s > 0; s >>= 1) {
        if (threadIdx.x < s) red[threadIdx.x] = fmaxf(red[threadIdx.x], red[threadIdx.x + s]);
        __syncthreads();
    }
    if (threadIdx.x == 0) g_pool[(b * HC + cc) * 4 + q] = red[0];
}

// ---------------------------------------------------------------------------
// Kernel 2: tiny 2x2 dwconvs + base[b][q][o]
// ---------------------------------------------------------------------------
__global__ __launch_bounds__(512) void base_kernel(
    const float* __restrict__ w2, const float* __restrict__ b2,
    const float* __restrict__ w3, const float* __restrict__ b3,
    const float* __restrict__ w4, const float* __restrict__ b4,
    const float* __restrict__ wa, const float* __restrict__ ba)
{
    int b  = blockIdx.x >> 2;
    int oc = (blockIdx.x & 3) * 128;
    __shared__ float catlow[256][4];
    int t = threadIdx.x;
    if (t < 256) {
        const float* wp;
        float bias;
        if (t < 128)       { wp = w2 + t * 9;         bias = b2[t];        }
        else if (t < 192)  { wp = w3 + (t - 128) * 9; bias = b3[t - 128]; }
        else               { wp = w4 + (t - 192) * 9; bias = b4[t - 192]; }
        float i00 = g_pool[(b * HC + t) * 4 + 0];
        float i01 = g_pool[(b * HC + t) * 4 + 1];
        float i10 = g_pool[(b * HC + t) * 4 + 2];
        float i11 = g_pool[(b * HC + t) * 4 + 3];
        catlow[t][0] = i00*wp[4] + i01*wp[5] + i10*wp[7] + i11*wp[8] + bias;
        catlow[t][1] = i00*wp[3] + i01*wp[4] + i10*wp[6] + i11*wp[7] + bias;
        catlow[t][2] = i00*wp[1] + i01*wp[2] + i10*wp[4] + i11*wp[5] + bias;
        catlow[t][3] = i00*wp[0] + i01*wp[1] + i10*wp[3] + i11*wp[4] + bias;
    }
    __syncthreads();
    int o    = oc + (t >> 2);
    int part = t & 3;
    int cc0  = part * 64;
    float a0 = 0.f, a1 = 0.f, a2 = 0.f, a3 = 0.f;
    #pragma unroll 4
    for (int cc = cc0; cc < cc0 + 64; ++cc) {
        float wv = wa[o * CFULL + 256 + cc];
        a0 = fmaf(wv, catlow[cc][0], a0);
        a1 = fmaf(wv, catlow[cc][1], a1);
        a2 = fmaf(wv, catlow[cc][2], a2);
        a3 = fmaf(wv, catlow[cc][3], a3);
    }
    #pragma unroll
    for (int off = 1; off < 4; off <<= 1) {
        a0 += __shfl_xor_sync(0xffffffff, a0, off);
        a1 += __shfl_xor_sync(0xffffffff, a1, off);
        a2 += __shfl_xor_sync(0xffffffff, a2, off);
        a3 += __shfl_xor_sync(0xffffffff, a3, off);
    }
    if (part == 0) {
        float bav = ba[o];
        g_base[(b * 4 + 0) * CFULL + o] = a0 + bav;
        g_base[(b * 4 + 1) * CFULL + o] = a1 + bav;
        g_base[(b * 4 + 2) * CFULL + o] = a2 + bav;
        g_base[(b * 4 + 3) * CFULL + o] = a3 + bav;
    }
}

// ---------------------------------------------------------------------------
// Kernel 3: dwconv3x3 on channels 0..255 -> g_x1 TRANSPOSED [b][n][k].
// block = (b, row r, k-block of 32). thread = (k = t&31, col-group ng = t>>5).
// Register row windows; per-c warp stores are 128B k-contiguous (coalesced).
// ---------------------------------------------------------------------------
__global__ __launch_bounds__(256) void dwconv_kernel(
    const float* __restrict__ x, const float* __restrict__ w1, const float* __restrict__ b1)
{
    int blk = blockIdx.x;
    int kb  = blk & 7;
    int r   = (blk >> 3) & 127;
    int b   = blk >> 10;
    int k   = kb * 32 + (threadIdx.x & 31);
    int ng  = threadIdx.x >> 5;     // 0..7
    int c0  = ng * 16;

    const float* xin = x + ((size_t)(b * CFULL + k)) * HW;
    const float* wp = w1 + k * 9;
    float w00 = wp[0], w01 = wp[1], w02 = wp[2];
    float w10 = wp[3], w11 = wp[4], w12 = wp[5];
    float w20 = wp[6], w21 = wp[7], w22 = wp[8];
    float bias = b1[k];

    // row[dr][0..17] covers cols c0-1 .. c0+16 (zero-padded at edges)
    float row[3][18];
    #pragma unroll
    for (int dr = 0; dr < 3; ++dr) {
        int gr = r + dr - 1;
        if (gr < 0 || gr >= HH) {
            #pragma unroll
            for (int i = 0; i < 18; ++i) row[dr][i] = 0.f;
        } else {
            const float* rp = xin + gr * WW + c0;
            #pragma unroll
            for (int j = 0; j < 4; ++j) {
                float4 v = *reinterpret_cast<const float4*>(rp + j * 4);
                row[dr][1 + j * 4 + 0] = v.x;
                row[dr][1 + j * 4 + 1] = v.y;
                row[dr][1 + j * 4 + 2] = v.z;
                row[dr][1 + j * 4 + 3] = v.w;
            }
            row[dr][0]  = (c0 > 0)        ? rp[-1] : 0.f;
            row[dr][17] = (c0 + 16 < WW)  ? rp[16] : 0.f;
        }
    }

    float* outp = g_x1 + (((size_t)b * HW) + (size_t)r * WW + c0) * HC + k;
    #pragma unroll
    for (int c = 0; c < 16; ++c) {
        float acc = bias;
        acc = fmaf(w00, row[0][c],     acc);
        acc = fmaf(w01, row[0][c + 1], acc);
        acc = fmaf(w02, row[0][c + 2], acc);
        acc = fmaf(w10, row[1][c],     acc);
        acc = fmaf(w11, row[1][c + 1], acc);
        acc = fmaf(w12, row[1][c + 2], acc);
        acc = fmaf(w20, row[2][c],     acc);
        acc = fmaf(w21, row[2][c + 1], acc);
        acc = fmaf(w22, row[2][c + 2], acc);
        outp[(size_t)c * HC] = acc;
    }
}

// ---------------------------------------------------------------------------
// Kernel 4: tf32 GEMM via ldmatrix.x4 fragments + cp.async, 1 sync/iter.
// A = wa[m][k] (K-major), B = g_x1[n][k] (K-major). D = A * B^T.
// Block 128x128, BK=32, 8 warps (4M x 2N), mma.m16n8k8 tf32.
// ---------------------------------------------------------------------------
__device__ __forceinline__ float gelu_exact(float v) {
    return 0.5f * v * (1.0f + erff(v * 0.70710678118654752f));
}
__device__ __forceinline__ void mma_tf32(float (&d)[4], const uint32_t (&a)[4],
                                         uint32_t b0, uint32_t b1) {
    asm volatile(
        "mma.sync.aligned.m16n8k8.row.col.f32.tf32.tf32.f32 "
        "{%0,%1,%2,%3}, {%4,%5,%6,%7}, {%8,%9}, {%0,%1,%2,%3};"
        : "+f"(d[0]), "+f"(d[1]), "+f"(d[2]), "+f"(d[3])
        : "r"(a[0]), "r"(a[1]), "r"(a[2]), "r"(a[3]), "r"(b0), "r"(b1));
}
__device__ __forceinline__ void cp_async16(uint32_t dst, const void* src) {
    asm volatile("cp.async.cg.shared.global [%0], [%1], 16;" :: "r"(dst), "l"(src));
}
__device__ __forceinline__ void ldsm4(uint32_t (&r)[4], uint32_t addr) {
    asm volatile("ldmatrix.sync.aligned.m8n8.x4.shared.b16 {%0,%1,%2,%3}, [%4];"
                 : "=r"(r[0]), "=r"(r[1]), "=r"(r[2]), "=r"(r[3]) : "r"(addr));
}

#define BM 128
#define BN 128
#define BK 32
#define TSTRIDE 36
#define T_ELEMS (128 * TSTRIDE)            // 4608 (both As and Bs tiles)
#define GEMM_SMEM_BYTES (4 * T_ELEMS * 4)  // 73728

__global__ __launch_bounds__(256, 2) void gemm_gelu_kernel(
    const float* __restrict__ x, const float* __restrict__ wa, float* __restrict__ out)
{
    extern __shared__ uint32_t smem[];
    uint32_t* As0 = smem;                  // [2][128 m][36]
    uint32_t* Bs0 = smem + 2 * T_ELEMS;    // [2][128 n][36]

    int b  = blockIdx.z;
    int bx = blockIdx.x;                   // image row; n0 = bx*128
    int m0 = blockIdx.y * BM;
    int tid = threadIdx.x;
    int lane = tid & 31, warp = tid >> 5;
    int warpM = warp & 3;
    int warpN = warp >> 2;

    const float* x1b = g_x1 + (size_t)b * HW * HC;
    int n0 = bx * BN;

    // cp.async indices: 1024 chunks of 16B per tile, 4 per thread
    int rowi[4], kci[4];
    #pragma unroll
    for (int j = 0; j < 4; ++j) {
        int idx = tid + 256 * j;
        rowi[j] = idx >> 3;
        kci[j]  = (idx & 7) * 4;
    }

    uint32_t as_base = (uint32_t)__cvta_generic_to_shared(As0);
    uint32_t bs_base = (uint32_t)__cvta_generic_to_shared(Bs0);

    auto load_stage = [&](int k0, int s) {
        #pragma unroll
        for (int j = 0; j < 4; ++j) {
            const float* src = wa + (size_t)(m0 + rowi[j]) * CFULL + k0 + kci[j];
            uint32_t dst = as_base + (s * T_ELEMS + rowi[j] * TSTRIDE + kci[j]) * 4;
            cp_async16(dst, src);
        }
        #pragma unroll
        for (int j = 0; j < 4; ++j) {
            const float* src = x1b + (size_t)(n0 + rowi[j]) * HC + k0 + kci[j];
            uint32_t dst = bs_base + (s * T_ELEMS + rowi[j] * TSTRIDE + kci[j]) * 4;
            cp_async16(dst, src);
        }
        asm volatile("cp.async.commit_group;" ::: "memory");
    };

    // ldmatrix per-lane offsets (in elements)
    int j4 = lane >> 3;                      // which 8x8 tile this lane addresses
    int a_row = ((j4 & 1) * 8) + (lane & 7); // tiles 1,3 -> +8 rows
    int a_col = (j4 >> 1) * 4;               // tiles 2,3 -> +4 cols
    int b_row = ((j4 >> 1) * 8) + (lane & 7);// tiles 2,3 -> +8 rows (odd nt)
    int b_col = (j4 & 1) * 4;                // tiles 1,3 -> +4 cols
    int aoff0 = (warpM * 32 +  0 + a_row) * TSTRIDE + a_col;
    int aoff1 = (warpM * 32 + 16 + a_row) * TSTRIDE + a_col;
    int boff[4];
    #pragma unroll
    for (int ntp = 0; ntp < 4; ++ntp)
        boff[ntp] = (warpN * 64 + ntp * 16 + b_row) * TSTRIDE + b_col;

    float acc[2][8][4] = {};

    load_stage(0, 0);

    #pragma unroll 1
    for (int it = 0; it < HC / BK; ++it) {
        asm volatile("cp.async.wait_group 0;" ::: "memory");
        __syncthreads();
        if (it < HC / BK - 1) load_stage((it + 1) * BK, (it + 1) & 1);

        int s = it & 1;
        uint32_t aB = as_base + s * T_ELEMS * 4;
        uint32_t bB = bs_base + s * T_ELEMS * 4;

        #pragma unroll
        for (int ks = 0; ks < 4; ++ks) {
            uint32_t af[2][4];
            ldsm4(af[0], aB + (aoff0 + ks * 8) * 4);
            ldsm4(af[1], aB + (aoff1 + ks * 8) * 4);
            #pragma unroll
            for (int ntp = 0; ntp < 4; ++ntp) {
                uint32_t bb[4];
                ldsm4(bb, bB + (boff[ntp] + ks * 8) * 4);
                mma_tf32(acc[0][2 * ntp    ], af[0], bb[0], bb[1]);
                mma_tf32(acc[1][2 * ntp    ], af[1], bb[0], bb[1]);
                mma_tf32(acc[0][2 * ntp + 1], af[0], bb[2], bb[3]);
                mma_tf32(acc[1][2 * ntp + 1], af[1], bb[2], bb[3]);
            }
        }
    }

    // Epilogue: +base, exact GELU, gate by x, store.
    int q = ((bx >= 64) ? 2 : 0) + warpN;
    const float* basep = g_base + (b * 4 + q) * CFULL;

    #pragma unroll
    for (int mt = 0; mt < 2; ++mt) {
        int mrow0 = m0 + warpM * 32 + mt * 16 + (lane >> 2);
        int mrow1 = mrow0 + 8;
        float bs0 = basep[mrow0];
        float bs1 = basep[mrow1];
        #pragma unroll
        for (int nt = 0; nt < 8; ++nt) {
            int n = n0 + warpN * 64 + nt * 8 + (lane & 3) * 2;
            size_t off0 = ((size_t)(b * CFULL + mrow0)) * HW + n;
            size_t off1 = ((size_t)(b * CFULL + mrow1)) * HW + n;
            float2 xv0 = *reinterpret_cast<const float2*>(x + off0);
            float2 xv1 = *reinterpret_cast<const float2*>(x + off1);
            float2 r0, r1;
            r0.x = gelu_exact(acc[mt][nt][0] + bs0) * xv0.x;
            r0.y = gelu_exact(acc[mt][nt][1] + bs0) * xv0.y;
            r1.x = gelu_exact(acc[mt][nt][2] + bs1) * xv1.x;
            r1.y = gelu_exact(acc[mt][nt][3] + bs1) * xv1.y;
            *reinterpret_cast<float2*>(out + off0) = r0;
            *reinterpret_cast<float2*>(out + off1) = r1;
        }
    }
}

// ---------------------------------------------------------------------------
extern "C" void kernel_launch(void* const* d_in, const int* in_sizes, int n_in,
                              void* d_out, int out_size) {
    const float* x  = (const float*)d_in[0];
    const float* w1 = (const float*)d_in[1];
    const float* b1 = (const float*)d_in[2];
    const float* w2 = (const float*)d_in[3];
    const float* b2 = (const float*)d_in[4];
    const float* w3 = (const float*)d_in[5];
    const float* b3 = (const float*)d_in[6];
    const float* w4 = (const float*)d_in[7];
    const float* b4 = (const float*)d_in[8];
    const float* wa = (const float*)d_in[9];
    const float* ba = (const float*)d_in[10];
    float* out = (float*)d_out;

    cudaFuncSetAttribute(gemm_gelu_kernel,
                         cudaFuncAttributeMaxDynamicSharedMemorySize, GEMM_SMEM_BYTES);

    pool_kernel<<<BATCH * HC * 4, 256>>>(x);
    base_kernel<<<16, 512>>>(w2, b2, w3, b3, w4, b4, wa, ba);
    dwconv_kernel<<<BATCH * 128 * 8, 256>>>(x, w1, b1);
    gemm_gelu_kernel<<<dim3(HW / BN, CFULL / BM, BATCH), 256, GEMM_SMEM_BYTES>>>(x, wa, out);
}